// round 8
// baseline (speedup 1.0000x reference)
#include <cuda_runtime.h>
#include <cuda_bf16.h>
#include <cstdint>

// NLTKHierarchicalSoftmax: B=4096, NHID=512, BR=32, DEPTH=3
// Round 7: cp.async W pipelines.
//  bids [0,128):   level 2 — 8 buckets/CTA, warp-per-bucket, per-warp 4-slot
//                  cp.async W pipeline (16h chunks, prefetch distance 2)
//  bids [128,192): level 0 — 64 samples/CTA, CTA-shared 4-slot cp.async W
//                  pipeline (32h chunks), node 0
//  bids [192,256): level 1 — CTA per (node, sample-parity), same CTA pipeline
// W always read from smem (LDS, 29cyc) in the FMA loop; gmem->smem via
// cp.async.cg (L1-bypass). Last CTA computes the 3-factor product.

#define FULL 0xffffffffu
#define NHID 512
#define BR 32
#define BTOT 4096
#define WNODE (NHID*BR)
#define NCTA 256
#define CAP1 128
#define CAP2 64
#define DSMEM_BYTES (96*1024)

__device__ float g_p[3 * BTOT];
__device__ int g_done;            // zero-init; reset by last CTA each launch

typedef unsigned long long u64t;

__device__ __forceinline__ u64t ffma2(u64t a, u64t b, u64t c)
{
    u64t d;
    asm("fma.rn.f32x2 %0, %1, %2, %3;" : "=l"(d) : "l"(a), "l"(b), "l"(c));
    return d;
}
__device__ __forceinline__ u64t packf2(float lo, float hi)
{
    u64t d;
    asm("mov.b64 %0, {%1, %2};" : "=l"(d) : "f"(lo), "f"(hi));
    return d;
}
__device__ __forceinline__ float2 unpackf2(u64t v)
{
    float2 r;
    asm("mov.b64 {%0, %1}, %2;" : "=f"(r.x), "=f"(r.y) : "l"(v));
    return r;
}
__device__ __forceinline__ unsigned sm32(const void* p)
{
    return (unsigned)__cvta_generic_to_shared(p);
}
__device__ __forceinline__ void cp16(unsigned d, const void* s)
{
    asm volatile("cp.async.cg.shared.global [%0], [%1], 16;"
                 :: "r"(d), "l"(s));
}
__device__ __forceinline__ void cp_commit()
{
    asm volatile("cp.async.commit_group;");
}
__device__ __forceinline__ void cp_wait2()
{
    asm volatile("cp.async.wait_group 2;" ::: "memory");
}

// 16h x 32col chunk from smem W, TS samples. lane = column.
template<int TS>
__device__ __forceinline__ void compute16(u64t* acc2, const float* __restrict__ wsm,
                                          float (*xsm)[128], int hloc, int lane)
{
    u64t wp[8];
    #pragma unroll
    for (int k = 0; k < 8; k++) {
        float wa = wsm[(2 * k) * 32 + lane];
        float wb = wsm[(2 * k + 1) * 32 + lane];
        wp[k] = packf2(wa, wb);
    }
    #pragma unroll
    for (int q = 0; q < 4; q++) {
        #pragma unroll
        for (int s = 0; s < TS; s++) {
            ulonglong2 xq = *(const ulonglong2*)&xsm[s][hloc + q * 4];
            acc2[s] = ffma2(xq.x, wp[2 * q], acc2[s]);
            acc2[s] = ffma2(xq.y, wp[2 * q + 1], acc2[s]);
        }
    }
}

template<int TS>
__device__ __forceinline__ void softmax_emit(u64t* acc2, unsigned msk,
                                             const int* bs, const int* step,
                                             int lane, float* __restrict__ pout)
{
    #pragma unroll
    for (int s = 0; s < TS; s++) {
        if (msk & (1u << s)) {
            float2 h = unpackf2(acc2[s]);
            float a = h.x + h.y;
            float m = a;
            #pragma unroll
            for (int o = 16; o > 0; o >>= 1)
                m = fmaxf(m, __shfl_xor_sync(FULL, m, o));
            float e = __expf(a - m);
            float sum = e;
            #pragma unroll
            for (int o = 16; o > 0; o >>= 1)
                sum += __shfl_xor_sync(FULL, sum, o);
            float est = __shfl_sync(FULL, e, step[s]);
            if (lane == 0) pout[bs[s]] = est / sum;
        }
    }
}

// ---------------- CTA-cooperative pass (L0/L1): shared node -------------------
// 16 chunks of 32h; Wbuf = 4 slots x 1024 floats; prefetch distance 2.
__device__ void cta_pass(const float* __restrict__ x, const float* __restrict__ Wn,
                         const int* bs, unsigned msk, const int* step,
                         int lane, int tid, float (*xsm)[128],
                         float* __restrict__ Wbuf, float* __restrict__ pout)
{
    u64t acc2[8];
    #pragma unroll
    for (int s = 0; s < 8; s++) acc2[s] = 0ull;

    #pragma unroll
    for (int d = 0; d < 2; d++) {                 // prologue: chunks 0,1
        cp16(sm32(Wbuf + d * 1024 + tid * 4), Wn + d * 1024 + tid * 4);
        cp_commit();
    }

    #pragma unroll 1
    for (int g = 0; g < 16; g++) {
        if ((g & 3) == 0) {                       // stage 128h of x per warp
            __syncwarp();
            #pragma unroll
            for (int s = 0; s < 8; s++) {
                float4 xv = *(const float4*)(x + (size_t)bs[s] * NHID
                                             + (g >> 2) * 128 + lane * 4);
                *(float4*)&xsm[s][lane * 4] = xv;
            }
            __syncwarp();
        }
        int nx = g + 2;
        if (nx < 16)
            cp16(sm32(Wbuf + (nx & 3) * 1024 + tid * 4),
                 Wn + nx * 1024 + tid * 4);
        cp_commit();
        cp_wait2();
        __syncthreads();
        const float* wch = Wbuf + (g & 3) * 1024;
        int hloc = (g & 3) * 32;
        compute16<8>(acc2, wch,       xsm, hloc,      lane);
        compute16<8>(acc2, wch + 512, xsm, hloc + 16, lane);
    }
    softmax_emit<8>(acc2, msk, bs, step, lane, pout);
}

// ---------------- per-warp pass (L2): warp-private node -----------------------
// 32 chunks of 16h; Wl = 4 slots x 512 floats (warp-private); distance 2.
template<int TS>
__device__ void warp_run(const float* __restrict__ x, const float* __restrict__ Wn,
                         const int* bs, unsigned msk, const int* step,
                         int lane, float (*xsm)[128], float* __restrict__ Wl,
                         float* __restrict__ pout)
{
    u64t acc2[TS];
    #pragma unroll
    for (int s = 0; s < TS; s++) acc2[s] = 0ull;

    #pragma unroll
    for (int d = 0; d < 2; d++) {                 // prologue: chunks 0,1
        #pragma unroll
        for (int j = 0; j < 4; j++)
            cp16(sm32(Wl + d * 512 + j * 128 + lane * 4),
                 Wn + d * 512 + j * 128 + lane * 4);
        cp_commit();
    }

    #pragma unroll 1
    for (int g = 0; g < 32; g++) {
        if ((g & 7) == 0) {                       // stage 128h of x
            __syncwarp();
            #pragma unroll
            for (int s = 0; s < TS; s++) {
                float4 xv = *(const float4*)(x + (size_t)bs[s] * NHID
                                             + (g >> 3) * 128 + lane * 4);
                *(float4*)&xsm[s][lane * 4] = xv;
            }
            __syncwarp();
        }
        int nx = g + 2;
        if (nx < 32) {
            #pragma unroll
            for (int j = 0; j < 4; j++)
                cp16(sm32(Wl + (nx & 3) * 512 + j * 128 + lane * 4),
                     Wn + nx * 512 + j * 128 + lane * 4);
        }
        cp_commit();
        cp_wait2();
        __syncwarp();
        compute16<TS>(acc2, Wl + (g & 3) * 512, xsm, (g & 7) * 16, lane);
    }
    softmax_emit<TS>(acc2, msk, bs, step, lane, pout);
    __syncwarp();
}

// ---------------- fused kernel ------------------------------------------------
__global__ void __launch_bounds__(256, 2) k_all(
    const float* __restrict__ x, const int* __restrict__ labels,
    const float* __restrict__ W, float* __restrict__ out, int B)
{
    extern __shared__ __align__(16) char dsm[];
    float (*xs_all)[8][128] = reinterpret_cast<float (*)[8][128]>(dsm);  // 32KB
    float* wreg = reinterpret_cast<float*>(dsm + 8 * 8 * 128 * 4);       // 64KB

    __shared__ int s_cnt[8];
    __shared__ int s_list[8][CAP2];
    __shared__ int s_l1list[CAP1];
    __shared__ int s_l1cnt;
    __shared__ int s_last;

    const int tid = threadIdx.x;
    const int lane = tid & 31;
    const int wid = tid >> 5;
    const int c = blockIdx.x;
    float (*xsm)[128] = xs_all[wid];

    if (c < 128) {
        // ---------------- level 2: buckets [8c, 8c+8) ----------------
        if (tid < 8) s_cnt[tid] = 0;
        __syncthreads();
        for (int i = tid; i < B; i += 256) {
            int key = __ldg(&labels[i]) >> 5;
            if ((key >> 3) == c) {
                int lb = key & 7;
                int pos = atomicAdd(&s_cnt[lb], 1);
                if (pos < CAP2) s_list[lb][pos] = i;
            }
        }
        __syncthreads();

        int C = min(s_cnt[wid], CAP2);
        const float* Wn = W + (size_t)(33 + 8 * c + wid) * WNODE;
        float* Wl = wreg + wid * 2048;   // 4 slots x 512 floats

        int t = 0;
        while (C - t > 0) {
            int G = min(8, C - t);
            if (G > 4) {
                int bs[8], step[8];
                #pragma unroll
                for (int s = 0; s < 8; s++) {
                    int b = s_list[wid][t + ((s < G) ? s : (G - 1))];
                    bs[s] = b;
                    step[s] = __ldg(&labels[b]) & 31;
                }
                unsigned msk = (G >= 8) ? 0xffu : ((1u << G) - 1u);
                warp_run<8>(x, Wn, bs, msk, step, lane, xsm, Wl, g_p + 2 * BTOT);
            } else {
                int bs[4], step[4];
                #pragma unroll
                for (int s = 0; s < 4; s++) {
                    int b = s_list[wid][t + ((s < G) ? s : (G - 1))];
                    bs[s] = b;
                    step[s] = __ldg(&labels[b]) & 31;
                }
                warp_run<4>(x, Wn, bs, (1u << G) - 1u, step, lane, xsm, Wl,
                            g_p + 2 * BTOT);
            }
            t += G;
        }
    } else if (c < 192) {
        // ---------------- level 0: node 0, natural order ----------------
        int s0 = (c - 128) * 64 + wid * 8;
        int bs[8], step[8];
        unsigned msk = 0;
        #pragma unroll
        for (int s = 0; s < 8; s++) {
            int b = min(s0 + s, B - 1);
            bs[s] = b;
            step[s] = (__ldg(&labels[b]) >> 10) & 31;
            if (s0 + s < B) msk |= 1u << s;
        }
        cta_pass(x, W, bs, msk, step, lane, tid, xsm, wreg, g_p);
    } else {
        // ---------------- level 1: CTA per (node, parity) ----------------
        int k = (c - 192) >> 1;
        int p = (c - 192) & 1;
        if (tid == 0) s_l1cnt = 0;
        __syncthreads();
        for (int i = tid; i < B; i += 256) {
            int lab = __ldg(&labels[i]);
            if ((lab >> 10) == k && (i & 1) == p) {
                int pos = atomicAdd(&s_l1cnt, 1);
                if (pos < CAP1) s_l1list[pos] = i;
            }
        }
        __syncthreads();

        int C = min(s_l1cnt, CAP1);
        int P = (C + 63) >> 6;                    // passes of 64 samples
        const float* Wn = W + (size_t)(1 + k) * WNODE;
        for (int q = 0; q < P; q++) {
            int t0 = q * 64 + wid * 8;
            int bs[8], step[8];
            unsigned msk = 0;
            #pragma unroll
            for (int s = 0; s < 8; s++) {
                int idx = t0 + s;
                int j = (idx < C) ? idx : (C - 1);
                int b = s_l1list[j];
                bs[s] = b;
                step[s] = (__ldg(&labels[b]) >> 5) & 31;
                if (idx < C) msk |= 1u << s;
            }
            cta_pass(x, Wn, bs, msk, step, lane, tid, xsm, wreg, g_p + BTOT);
        }
    }

    // ---------------- completion: last CTA computes the product --------------
    __syncthreads();
    __threadfence();
    if (tid == 0) {
        int old = atomicAdd(&g_done, 1);
        s_last = (old == NCTA - 1) ? 1 : 0;
    }
    __syncthreads();
    if (s_last) {
        __threadfence();
        for (int i = tid; i < B; i += 256)
            out[i] = g_p[i] * g_p[BTOT + i] * g_p[2 * BTOT + i];
        if (tid == 0) g_done = 0;   // reset for next graph replay
    }
}

extern "C" void kernel_launch(void* const* d_in, const int* in_sizes, int n_in,
                              void* d_out, int out_size)
{
    const float* x      = (const float*)d_in[0];
    const int*   labels = (const int*)d_in[1];
    const float* W      = (const float*)d_in[2];
    float* out = (float*)d_out;

    int B = in_sizes[1];  // 4096

    cudaFuncSetAttribute(k_all, cudaFuncAttributeMaxDynamicSharedMemorySize,
                         DSMEM_BYTES);
    k_all<<<NCTA, 256, DSMEM_BYTES>>>(x, labels, W, out, B);
}

// round 9
// speedup vs baseline: 1.6930x; 1.6930x over previous
#include <cuda_runtime.h>
#include <cuda_bf16.h>
#include <cstdint>

// NLTKHierarchicalSoftmax: B=4096, NHID=512, BR=32, DEPTH=3
// Round 9: R4 architecture (best measured) + col-pair W mapping.
//   k_sort: 1024-thread counting sort, batched loads (MLP=4)
//   k_work: 2048 warps; lane = (col-pair, h-parity); W via LDG.64 (f32x2
//           direct), x staged as duplicated float2 in smem by parity;
//           double-buffered W register prefetch; last CTA computes product.

#define FULL 0xffffffffu
#define NHID 512
#define BR 32
#define NB2 1024
#define BTOT 4096
#define WNODE (NHID*BR)
#define NL0 512
#define NL1 512
#define NCTA 256
#define XDS 132                      // float2 per sample: 2 planes x 66 (padded)
#define WARP_XD (8 * XDS)            // float2 per warp region
#define DSMEM_BYTES (8 * WARP_XD * 8)  // 8 warps * 1056 f2 * 8B = 67584

__device__ int g_off[NB2 + 1];
__device__ int g_sorted[BTOT];
__device__ float g_p[3 * BTOT];
__device__ int g_done;               // zero-init; reset by last CTA

typedef unsigned long long u64t;

__device__ __forceinline__ u64t ffma2(u64t a, u64t b, u64t c)
{
    u64t d;
    asm("fma.rn.f32x2 %0, %1, %2, %3;" : "=l"(d) : "l"(a), "l"(b), "l"(c));
    return d;
}
__device__ __forceinline__ float2 unpackf2(u64t v)
{
    float2 r;
    asm("mov.b64 {%0, %1}, %2;" : "=f"(r.x), "=f"(r.y) : "l"(v));
    return r;
}

// ---------------- counting sort (single CTA, 1024 thr, batched) ---------------
__global__ void __launch_bounds__(NB2) k_sort(const int* __restrict__ labels, int B)
{
    __shared__ int cnt[NB2];
    __shared__ int cur[NB2];
    __shared__ int wsum[32];
    int t = threadIdx.x;
    int lane = t & 31;
    int warp = t >> 5;

    cnt[t] = 0;
    __syncthreads();

    // histogram: 4 batched loads per thread (B = 4096)
    int l0 = (t          < B) ? __ldg(&labels[t])          : -1;
    int l1 = (t + 1024   < B) ? __ldg(&labels[t + 1024])   : -1;
    int l2 = (t + 2048   < B) ? __ldg(&labels[t + 2048])   : -1;
    int l3 = (t + 3072   < B) ? __ldg(&labels[t + 3072])   : -1;
    if (l0 >= 0) atomicAdd(&cnt[l0 >> 5], 1);
    if (l1 >= 0) atomicAdd(&cnt[l1 >> 5], 1);
    if (l2 >= 0) atomicAdd(&cnt[l2 >> 5], 1);
    if (l3 >= 0) atomicAdd(&cnt[l3 >> 5], 1);
    __syncthreads();

    // two-stage shuffle scan
    int v = cnt[t];
    int inc = v;
    #pragma unroll
    for (int o = 1; o < 32; o <<= 1) {
        int u = __shfl_up_sync(FULL, inc, o);
        if (lane >= o) inc += u;
    }
    if (lane == 31) wsum[warp] = inc;
    __syncthreads();
    if (t < 32) {
        int wv = wsum[t];
        int wi = wv;
        #pragma unroll
        for (int o = 1; o < 32; o <<= 1) {
            int u = __shfl_up_sync(FULL, wi, o);
            if (t >= o) wi += u;
        }
        wsum[t] = wi - wv;
    }
    __syncthreads();

    int excl = wsum[warp] + inc - v;
    g_off[t] = excl;
    cur[t] = excl;
    if (t == NB2 - 1) g_off[NB2] = excl + v;
    __syncthreads();

    // scatter (keys already in registers)
    if (l0 >= 0) g_sorted[atomicAdd(&cur[l0 >> 5], 1)] = t;
    if (l1 >= 0) g_sorted[atomicAdd(&cur[l1 >> 5], 1)] = t + 1024;
    if (l2 >= 0) g_sorted[atomicAdd(&cur[l2 >> 5], 1)] = t + 2048;
    if (l3 >= 0) g_sorted[atomicAdd(&cur[l3 >> 5], 1)] = t + 3072;
}

// ---------------- core: col-pair / parity GEMV run ----------------------------
// lane = (c = lane&15 -> cols 2c,2c+1 ; par = lane>>4 -> h parity).
// Chunk g (16 h): wr[j] = W[g*16+2j+par][2c..2c+1] as u64 (LDG.64, coalesced).
// x staged duplicated: xd[s][par*66 + i] = (x[2i+par], x[2i+par]).
template<int TS>
__device__ __forceinline__ void compute_chunk(
    u64t* acc2, const u64t* wr, const float2* __restrict__ xb)
{
    #pragma unroll
    for (int jj = 0; jj < 4; jj++) {
        #pragma unroll
        for (int s = 0; s < TS; s++) {
            ulonglong2 xq = *(const ulonglong2*)(xb + s * XDS + jj * 2);
            acc2[s] = ffma2(xq.x, wr[2 * jj], acc2[s]);
            acc2[s] = ffma2(xq.y, wr[2 * jj + 1], acc2[s]);
        }
    }
}

__device__ __forceinline__ void load_wchunk(u64t* wr, const float* __restrict__ Wp,
                                            int g)
{
    #pragma unroll
    for (int j = 0; j < 8; j++)
        wr[j] = __ldg((const u64t*)(Wp + g * 512 + j * 64));
}

template<int TS>
__device__ void run2(const float* __restrict__ x, const float* __restrict__ Wn,
                     const int* bs, unsigned msk, const int* step,
                     int lane, float2* __restrict__ xd, float* __restrict__ pout)
{
    const int c = lane & 15;
    const int par = lane >> 4;
    const float* Wp = Wn + par * 32 + 2 * c;

    u64t acc2[TS];
    #pragma unroll
    for (int s = 0; s < TS; s++) acc2[s] = 0ull;

    u64t wrA[8], wrB[8];
    load_wchunk(wrA, Wp, 0);

    #pragma unroll 1
    for (int g2 = 0; g2 < 16; g2++) {
        int g = g2 * 2;
        if ((g & 7) == 0) {                 // stage 128 h of x, dup + parity split
            int sc = g >> 3;
            __syncwarp();
            #pragma unroll
            for (int s = 0; s < TS; s++) {
                float4 v = *(const float4*)(x + (size_t)bs[s] * NHID
                                            + sc * 128 + lane * 4);
                float2* p0 = xd + s * XDS + 2 * lane;       // parity-0 plane
                float2* p1 = p0 + 66;                        // parity-1 plane
                *(float4*)p0 = make_float4(v.x, v.x, v.z, v.z);
                *(float4*)p1 = make_float4(v.y, v.y, v.w, v.w);
            }
            __syncwarp();
        }
        load_wchunk(wrB, Wp, g + 1);
        compute_chunk<TS>(acc2, wrA, xd + par * 66 + (g & 7) * 8);
        if (g + 2 < 32) load_wchunk(wrA, Wp, g + 2);
        compute_chunk<TS>(acc2, wrB, xd + par * 66 + ((g + 1) & 7) * 8);
    }

    // combine parity partials, softmax per sample
    #pragma unroll
    for (int s = 0; s < TS; s++) {
        float2 v = unpackf2(acc2[s]);
        v.x += __shfl_xor_sync(FULL, v.x, 16);
        v.y += __shfl_xor_sync(FULL, v.y, 16);
        if (msk & (1u << s)) {
            float m = fmaxf(v.x, v.y);
            #pragma unroll
            for (int o = 8; o > 0; o >>= 1)
                m = fmaxf(m, __shfl_xor_sync(FULL, m, o));
            float ex = __expf(v.x - m);
            float ey = __expf(v.y - m);
            float sum = ex + ey;
            #pragma unroll
            for (int o = 8; o > 0; o >>= 1)
                sum += __shfl_xor_sync(FULL, sum, o);
            float chosen = (step[s] & 1) ? ey : ex;
            float est = __shfl_sync(FULL, chosen, (step[s] >> 1) & 15);
            if (lane == 0) pout[bs[s]] = est / sum;
        }
    }
    __syncwarp();
}

// ---------------- work kernel --------------------------------------------------
__global__ void __launch_bounds__(256, 2) k_work(
    const float* __restrict__ x, const int* __restrict__ labels,
    const float* __restrict__ W, float* __restrict__ out, int B)
{
    extern __shared__ __align__(16) float2 xd_all[];
    __shared__ int s_last;

    const int tid = threadIdx.x;
    const int lane = tid & 31;
    const int wid = tid >> 5;
    int gw = blockIdx.x * 8 + wid;
    float2* xd = xd_all + wid * WARP_XD;

    if (gw < NL0) {
        // level 0: node 0, natural order
        int s0 = gw * 8;
        int bs[8], step[8];
        unsigned msk = 0;
        #pragma unroll
        for (int s = 0; s < 8; s++) {
            int b = min(s0 + s, B - 1);
            bs[s] = b;
            step[s] = (__ldg(&labels[b]) >> 10) & 31;
            if (s0 + s < B) msk |= 1u << s;
        }
        run2<8>(x, W, bs, msk, step, lane, xd, g_p);
    } else if (gw < NL0 + NL1) {
        // level 1: tiles of 8 sorted samples; node = 1 + (lab>>10)
        int s0 = (gw - NL0) * 8;
        int bs[8], step[8], node[8];
        #pragma unroll
        for (int s = 0; s < 8; s++) {
            int idx = min(s0 + s, B - 1);
            int b = __ldg(&g_sorted[idx]);
            bs[s] = b;
            int lab = __ldg(&labels[b]);
            node[s] = 1 + (lab >> 10);
            step[s] = (lab >> 5) & 31;
        }
        unsigned valid = (s0 + 8 <= B) ? 0xffu : ((1u << (B - s0)) - 1u);
        unsigned rem = valid;
        while (rem) {
            int src = __ffs(rem) - 1;
            int n = node[src];
            unsigned msk = 0;
            #pragma unroll
            for (int s = 0; s < 8; s++)
                if (node[s] == n) msk |= 1u << s;
            msk &= valid;
            run2<8>(x, W + (size_t)n * WNODE, bs, msk, step, lane, xd,
                    g_p + BTOT);
            rem &= ~msk;
        }
    } else if (gw < NL0 + NL1 + NB2) {
        // level 2: one warp per bucket (node = 33 + bucket)
        int w = gw - NL0 - NL1;
        int beg = __ldg(&g_off[w]);
        int end = __ldg(&g_off[w + 1]);
        const float* Wn = W + (size_t)(33 + w) * WNODE;

        int t = beg;
        while (end - t >= 5) {
            int G = min(8, end - t);
            int bs[8], step[8];
            #pragma unroll
            for (int s = 0; s < 8; s++) {
                int idx = t + ((s < G) ? s : (G - 1));
                int b = __ldg(&g_sorted[idx]);
                bs[s] = b;
                step[s] = __ldg(&labels[b]) & 31;
            }
            unsigned msk = (G >= 8) ? 0xffu : ((1u << G) - 1u);
            run2<8>(x, Wn, bs, msk, step, lane, xd, g_p + 2 * BTOT);
            t += G;
        }
        if (t < end) {
            int G = end - t;
            int bs[4], step[4];
            #pragma unroll
            for (int s = 0; s < 4; s++) {
                int idx = t + ((s < G) ? s : (G - 1));
                int b = __ldg(&g_sorted[idx]);
                bs[s] = b;
                step[s] = __ldg(&labels[b]) & 31;
            }
            run2<4>(x, Wn, bs, (1u << G) - 1u, step, lane, xd, g_p + 2 * BTOT);
        }
    }

    // completion: last CTA computes the 3-factor product
    __syncthreads();
    __threadfence();
    if (tid == 0) {
        int old = atomicAdd(&g_done, 1);
        s_last = (old == NCTA - 1) ? 1 : 0;
    }
    __syncthreads();
    if (s_last) {
        __threadfence();
        for (int i = tid; i < B; i += 256)
            out[i] = g_p[i] * g_p[BTOT + i] * g_p[2 * BTOT + i];
        if (tid == 0) g_done = 0;   // reset for next graph replay
    }
}

extern "C" void kernel_launch(void* const* d_in, const int* in_sizes, int n_in,
                              void* d_out, int out_size)
{
    const float* x      = (const float*)d_in[0];
    const int*   labels = (const int*)d_in[1];
    const float* W      = (const float*)d_in[2];
    float* out = (float*)d_out;

    int B = in_sizes[1];  // 4096

    k_sort<<<1, NB2>>>(labels, B);

    cudaFuncSetAttribute(k_work, cudaFuncAttributeMaxDynamicSharedMemorySize,
                         DSMEM_BYTES);
    k_work<<<NCTA, 256, DSMEM_BYTES>>>(x, labels, W, out, B);
}

// round 10
// speedup vs baseline: 1.9071x; 1.1265x over previous
#include <cuda_runtime.h>
#include <cuda_bf16.h>
#include <cstdint>

// NLTKHierarchicalSoftmax: B=4096, NHID=512, BR=32, DEPTH=3
// Round 10: Round-4 GEMV core verbatim (best measured) with
//   (a) batched-load counting sort (R9 version, ~3.5us)
//   (b) final 3-factor product fused into k_work via last-CTA pattern
// No inner-loop changes relative to R4.

#define FULL 0xffffffffu
#define NHID 512
#define BR 32
#define NB2 1024
#define BTOT 4096
#define WNODE (NHID*BR)
#define NL0 512
#define NL1 512
#define NCTA 256
#define WARPS_PER_CTA 8

__device__ int g_off[NB2 + 1];
__device__ int g_sorted[BTOT];
__device__ float g_p[3 * BTOT];
__device__ int g_done;               // zero-init; reset by last CTA

typedef unsigned long long u64t;

__device__ __forceinline__ u64t ffma2(u64t a, u64t b, u64t c)
{
    u64t d;
    asm("fma.rn.f32x2 %0, %1, %2, %3;" : "=l"(d) : "l"(a), "l"(b), "l"(c));
    return d;
}
__device__ __forceinline__ u64t packf2(float lo, float hi)
{
    u64t d;
    asm("mov.b64 %0, {%1, %2};" : "=l"(d) : "f"(lo), "f"(hi));
    return d;
}
__device__ __forceinline__ float2 unpackf2(u64t v)
{
    float2 r;
    asm("mov.b64 {%0, %1}, %2;" : "=f"(r.x), "=f"(r.y) : "l"(v));
    return r;
}

// ---------------- counting sort (single CTA, 1024 thr, batched loads) ---------
__global__ void __launch_bounds__(NB2) k_sort(const int* __restrict__ labels, int B)
{
    __shared__ int cnt[NB2];
    __shared__ int cur[NB2];
    __shared__ int wsum[32];
    int t = threadIdx.x;
    int lane = t & 31;
    int warp = t >> 5;

    cnt[t] = 0;
    __syncthreads();

    // histogram: 4 batched loads per thread (B = 4096)
    int l0 = (t        < B) ? __ldg(&labels[t])        : -1;
    int l1 = (t + 1024 < B) ? __ldg(&labels[t + 1024]) : -1;
    int l2 = (t + 2048 < B) ? __ldg(&labels[t + 2048]) : -1;
    int l3 = (t + 3072 < B) ? __ldg(&labels[t + 3072]) : -1;
    if (l0 >= 0) atomicAdd(&cnt[l0 >> 5], 1);
    if (l1 >= 0) atomicAdd(&cnt[l1 >> 5], 1);
    if (l2 >= 0) atomicAdd(&cnt[l2 >> 5], 1);
    if (l3 >= 0) atomicAdd(&cnt[l3 >> 5], 1);
    __syncthreads();

    // two-stage shuffle scan
    int v = cnt[t];
    int inc = v;
    #pragma unroll
    for (int o = 1; o < 32; o <<= 1) {
        int u = __shfl_up_sync(FULL, inc, o);
        if (lane >= o) inc += u;
    }
    if (lane == 31) wsum[warp] = inc;
    __syncthreads();
    if (t < 32) {
        int wv = wsum[t];
        int wi = wv;
        #pragma unroll
        for (int o = 1; o < 32; o <<= 1) {
            int u = __shfl_up_sync(FULL, wi, o);
            if (t >= o) wi += u;
        }
        wsum[t] = wi - wv;
    }
    __syncthreads();

    int excl = wsum[warp] + inc - v;
    g_off[t] = excl;
    cur[t] = excl;
    if (t == NB2 - 1) g_off[NB2] = excl + v;
    __syncthreads();

    if (l0 >= 0) g_sorted[atomicAdd(&cur[l0 >> 5], 1)] = t;
    if (l1 >= 0) g_sorted[atomicAdd(&cur[l1 >> 5], 1)] = t + 1024;
    if (l2 >= 0) g_sorted[atomicAdd(&cur[l2 >> 5], 1)] = t + 2048;
    if (l3 >= 0) g_sorted[atomicAdd(&cur[l3 >> 5], 1)] = t + 3072;
}

// ---------------- pipelined run processor (Round 4, verbatim) -----------------
template<int TS>
__device__ __forceinline__ void process_run(
    const float* __restrict__ x, const float* __restrict__ Wn,
    const int* bs, unsigned msk, const int* step,
    int lane, float (*xsm)[128], float* __restrict__ pout)
{
    u64t acc2[TS];
    #pragma unroll
    for (int s = 0; s < TS; s++) acc2[s] = 0ull;

    float wr[2][16];
    #pragma unroll
    for (int k = 0; k < 16; k++)
        wr[0][k] = __ldg(Wn + k * BR + lane);

    #pragma unroll 1
    for (int sc = 0; sc < 4; sc++) {            // 4 superchunks of 128 h
        __syncwarp();
        #pragma unroll
        for (int s = 0; s < TS; s++) {
            float4 xv = *(const float4*)(x + (size_t)bs[s] * NHID
                                         + sc * 128 + lane * 4);
            *(float4*)&xsm[s][lane * 4] = xv;
        }
        __syncwarp();

        #pragma unroll
        for (int sub = 0; sub < 8; sub++) {     // 8 subchunks of 16 h
            const int curb = sub & 1;
            const int subg = sc * 8 + sub;
            if (subg + 1 < 32) {                // prefetch next subchunk W
                int h0 = (subg + 1) * 16;
                #pragma unroll
                for (int k = 0; k < 16; k++)
                    wr[curb ^ 1][k] = __ldg(Wn + (h0 + k) * BR + lane);
            }
            u64t wp[8];
            #pragma unroll
            for (int k = 0; k < 8; k++)
                wp[k] = packf2(wr[curb][2 * k], wr[curb][2 * k + 1]);

            #pragma unroll
            for (int q = 0; q < 4; q++) {
                #pragma unroll
                for (int s = 0; s < TS; s++) {  // independent acc chains
                    ulonglong2 xq =
                        *(const ulonglong2*)&xsm[s][sub * 16 + q * 4];
                    acc2[s] = ffma2(xq.x, wp[2 * q], acc2[s]);
                    acc2[s] = ffma2(xq.y, wp[2 * q + 1], acc2[s]);
                }
            }
        }
    }

    // per-sample warp softmax over 32 columns (lane = column)
    #pragma unroll
    for (int s = 0; s < TS; s++) {
        if (msk & (1u << s)) {
            float2 h = unpackf2(acc2[s]);
            float acc = h.x + h.y;
            float m = acc;
            #pragma unroll
            for (int o = 16; o > 0; o >>= 1)
                m = fmaxf(m, __shfl_xor_sync(FULL, m, o));
            float e = __expf(acc - m);
            float sum = e;
            #pragma unroll
            for (int o = 16; o > 0; o >>= 1)
                sum += __shfl_xor_sync(FULL, sum, o);
            float est = __shfl_sync(FULL, e, step[s]);
            if (lane == 0) pout[bs[s]] = est / sum;
        }
    }
    __syncwarp();
}

// ---------------- work kernel (R4 partition + fused final) --------------------
__global__ void __launch_bounds__(32 * WARPS_PER_CTA, 2) k_work(
    const float* __restrict__ x, const int* __restrict__ labels,
    const float* __restrict__ W, float* __restrict__ out, int B)
{
    __shared__ __align__(16) float xs_tile[WARPS_PER_CTA][8][128];
    __shared__ int s_last;

    const int tid = threadIdx.x;
    const int lane = tid & 31;
    const int wid = tid >> 5;
    int gw = blockIdx.x * WARPS_PER_CTA + wid;
    float (*xsm)[128] = xs_tile[wid];

    if (gw < NL0) {
        // level 0: node 0, natural order (no sort dependency)
        int s0 = gw * 8;
        int bs[8], step[8];
        unsigned msk = 0;
        #pragma unroll
        for (int s = 0; s < 8; s++) {
            int b = min(s0 + s, B - 1);
            bs[s] = b;
            step[s] = (__ldg(&labels[b]) >> 10) & 31;
            if (s0 + s < B) msk |= 1u << s;
        }
        process_run<8>(x, W, bs, msk, step, lane, xsm, g_p);
    } else if (gw < NL0 + NL1) {
        // level 1: tiles of 8 consecutive sorted samples; node = 1 + (lab>>10)
        int s0 = (gw - NL0) * 8;
        int bs[8], step[8], node[8];
        #pragma unroll
        for (int s = 0; s < 8; s++) {
            int idx = min(s0 + s, B - 1);
            int b = __ldg(&g_sorted[idx]);
            bs[s] = b;
            int lab = __ldg(&labels[b]);
            node[s] = 1 + (lab >> 10);
            step[s] = (lab >> 5) & 31;
        }
        unsigned valid = (s0 + 8 <= B) ? 0xffu : ((1u << (B - s0)) - 1u);
        unsigned rem = valid;
        while (rem) {
            int src = __ffs(rem) - 1;
            int n = node[src];
            unsigned msk = 0;
            #pragma unroll
            for (int s = 0; s < 8; s++)
                if (node[s] == n) msk |= 1u << s;
            msk &= valid;
            process_run<8>(x, W + (size_t)n * WNODE, bs, msk, step, lane, xsm,
                           g_p + BTOT);
            rem &= ~msk;
        }
    } else if (gw < NL0 + NL1 + NB2) {
        // level 2: one warp per bucket (node = 33 + bucket)
        int w = gw - NL0 - NL1;
        int beg = __ldg(&g_off[w]);
        int end = __ldg(&g_off[w + 1]);
        const float* Wn = W + (size_t)(33 + w) * WNODE;

        int t = beg;
        while (end - t >= 5) {
            int G = min(8, end - t);
            int bs[8], step[8];
            #pragma unroll
            for (int s = 0; s < 8; s++) {
                int idx = t + ((s < G) ? s : (G - 1));
                int b = __ldg(&g_sorted[idx]);
                bs[s] = b;
                step[s] = __ldg(&labels[b]) & 31;
            }
            unsigned msk = (G >= 8) ? 0xffu : ((1u << G) - 1u);
            process_run<8>(x, Wn, bs, msk, step, lane, xsm, g_p + 2 * BTOT);
            t += G;
        }
        if (t < end) {
            int G = end - t;
            int bs[4], step[4];
            #pragma unroll
            for (int s = 0; s < 4; s++) {
                int idx = t + ((s < G) ? s : (G - 1));
                int b = __ldg(&g_sorted[idx]);
                bs[s] = b;
                step[s] = __ldg(&labels[b]) & 31;
            }
            process_run<4>(x, Wn, bs, (1u << G) - 1u, step, lane, xsm,
                           g_p + 2 * BTOT);
        }
    }

    // completion: last CTA computes the 3-factor product
    __syncthreads();
    __threadfence();
    if (tid == 0) {
        int old = atomicAdd(&g_done, 1);
        s_last = (old == NCTA - 1) ? 1 : 0;
    }
    __syncthreads();
    if (s_last) {
        __threadfence();
        for (int i = tid; i < B; i += 256)
            out[i] = g_p[i] * g_p[BTOT + i] * g_p[2 * BTOT + i];
        if (tid == 0) g_done = 0;   // reset for next graph replay
    }
}

extern "C" void kernel_launch(void* const* d_in, const int* in_sizes, int n_in,
                              void* d_out, int out_size)
{
    const float* x      = (const float*)d_in[0];
    const int*   labels = (const int*)d_in[1];
    const float* W      = (const float*)d_in[2];
    float* out = (float*)d_out;

    int B = in_sizes[1];  // 4096

    k_sort<<<1, NB2>>>(labels, B);
    k_work<<<NCTA, 256>>>(x, labels, W, out, B);
}